// round 9
// baseline (speedup 1.0000x reference)
#include <cuda_runtime.h>
#include <cuda_bf16.h>

#define NNODES 512
#define NIN    256
#define NOUT   256
#define NT     32      // 512/16 node tiles
#define TS     16      // writer tile size

// Split-K partial buffers: A = A0 + A1 (bias folded into A0), B = B0 + B1.
__device__ float g_A0[NNODES * NOUT];
__device__ float g_A1[NNODES * NOUT];
__device__ float g_B0[NNODES * NOUT];
__device__ float g_B1[NNODES * NOUT];

// ---------------------------------------------------------------------------
// Kernel 1: split-K GEMM partials, register double-buffered K-chunks.
//   z = half*2 + ks. C_part[i,o] = sum_{k in chunk ks} x[i,k]*W[o, half*256+k]
// ---------------------------------------------------------------------------
__global__ void __launch_bounds__(128)
gemm_ab_kernel(const float* __restrict__ x,
               const float* __restrict__ W,
               const float* __restrict__ b)
{
    const int z    = blockIdx.z;
    const int half = z >> 1;                  // 0: A, 1: B
    const int ks   = z & 1;                   // K-split index
    const int i0   = blockIdx.y * 32;
    const int o0   = blockIdx.x * 32;
    const int kbase = ks * 128;
    const int woff  = half * NIN;

    __shared__ __align__(16) float xs[32 * 34];  // [k][i]
    __shared__ __align__(16) float ws[32 * 36];  // [k][o]

    const int tid = threadIdx.x;
    const int tx  = tid & 7;    // o-thread: 4 cols
    const int ty  = tid >> 3;   // i-thread: 2 rows

    // per-thread load coordinates (2 float4 slots each for x and W tiles)
    const int lr0 = tid >> 3;               // slot 0 row (x: i, W: o)
    const int lq0 = tid & 7;                // slot 0 k-quad
    const int lr1 = (tid + 128) >> 3;
    const int lq1 = (tid + 128) & 7;

    float4 vx[2][2], vw[2][2];

    // prefetch chunk 0
    {
        const int k0 = kbase;
        vx[0][0] = *reinterpret_cast<const float4*>(&x[(i0 + lr0) * NIN + k0 + lq0 * 4]);
        vx[0][1] = *reinterpret_cast<const float4*>(&x[(i0 + lr1) * NIN + k0 + lq1 * 4]);
        vw[0][0] = *reinterpret_cast<const float4*>(&W[(o0 + lr0) * (2 * NIN) + woff + k0 + lq0 * 4]);
        vw[0][1] = *reinterpret_cast<const float4*>(&W[(o0 + lr1) * (2 * NIN) + woff + k0 + lq1 * 4]);
    }

    float acc[2][4] = {{0.f,0.f,0.f,0.f},{0.f,0.f,0.f,0.f}};

    #pragma unroll
    for (int ch = 0; ch < 4; ch++) {
        const int cur = ch & 1;
        // scatter prefetched regs into smem (transposed)
        {
            float4 v = vx[cur][0];
            xs[(lq0 * 4 + 0) * 34 + lr0] = v.x;
            xs[(lq0 * 4 + 1) * 34 + lr0] = v.y;
            xs[(lq0 * 4 + 2) * 34 + lr0] = v.z;
            xs[(lq0 * 4 + 3) * 34 + lr0] = v.w;
            v = vx[cur][1];
            xs[(lq1 * 4 + 0) * 34 + lr1] = v.x;
            xs[(lq1 * 4 + 1) * 34 + lr1] = v.y;
            xs[(lq1 * 4 + 2) * 34 + lr1] = v.z;
            xs[(lq1 * 4 + 3) * 34 + lr1] = v.w;
            v = vw[cur][0];
            ws[(lq0 * 4 + 0) * 36 + lr0] = v.x;
            ws[(lq0 * 4 + 1) * 36 + lr0] = v.y;
            ws[(lq0 * 4 + 2) * 36 + lr0] = v.z;
            ws[(lq0 * 4 + 3) * 36 + lr0] = v.w;
            v = vw[cur][1];
            ws[(lq1 * 4 + 0) * 36 + lr1] = v.x;
            ws[(lq1 * 4 + 1) * 36 + lr1] = v.y;
            ws[(lq1 * 4 + 2) * 36 + lr1] = v.z;
            ws[(lq1 * 4 + 3) * 36 + lr1] = v.w;
        }
        __syncthreads();

        // prefetch next chunk while computing on smem
        if (ch < 3) {
            const int nxt = cur ^ 1;
            const int k0  = kbase + (ch + 1) * 32;
            vx[nxt][0] = *reinterpret_cast<const float4*>(&x[(i0 + lr0) * NIN + k0 + lq0 * 4]);
            vx[nxt][1] = *reinterpret_cast<const float4*>(&x[(i0 + lr1) * NIN + k0 + lq1 * 4]);
            vw[nxt][0] = *reinterpret_cast<const float4*>(&W[(o0 + lr0) * (2 * NIN) + woff + k0 + lq0 * 4]);
            vw[nxt][1] = *reinterpret_cast<const float4*>(&W[(o0 + lr1) * (2 * NIN) + woff + k0 + lq1 * 4]);
        }

        #pragma unroll
        for (int kk = 0; kk < 32; kk++) {
            float2 a  = *reinterpret_cast<const float2*>(&xs[kk * 34 + ty * 2]);
            float4 wq = *reinterpret_cast<const float4*>(&ws[kk * 36 + tx * 4]);
            acc[0][0] += a.x * wq.x;
            acc[0][1] += a.x * wq.y;
            acc[0][2] += a.x * wq.z;
            acc[0][3] += a.x * wq.w;
            acc[1][0] += a.y * wq.x;
            acc[1][1] += a.y * wq.y;
            acc[1][2] += a.y * wq.z;
            acc[1][3] += a.y * wq.w;
        }
        __syncthreads();
    }

    float4 bias = make_float4(0.f, 0.f, 0.f, 0.f);
    if (half == 0 && ks == 0)
        bias = *reinterpret_cast<const float4*>(&b[o0 + tx * 4]);

    float* dst = (half == 0) ? (ks == 0 ? g_A0 : g_A1)
                             : (ks == 0 ? g_B0 : g_B1);
    #pragma unroll
    for (int r = 0; r < 2; r++) {
        int i = i0 + ty * 2 + r;
        float4 outv = make_float4(acc[r][0] + bias.x,
                                  acc[r][1] + bias.y,
                                  acc[r][2] + bias.z,
                                  acc[r][3] + bias.w);
        *reinterpret_cast<float4*>(&dst[i * NOUT + o0 + tx * 4]) = outv;
    }

    // PDL: writes above are visible to the dependent grid's griddepcontrol.wait
    asm volatile("griddepcontrol.launch_dependents;" ::: "memory");
}

// ---------------------------------------------------------------------------
// Kernel 2: symmetric tile writer, uniform 1KB-stride store walks.
//   All 1024 blocks active (lower->upper remap). Role swap for mirror blocks:
//     non-mirror: regs = A rows (outer i), smem = B tile, write out[i, j0+t]
//     mirror:     regs = B rows (outer j), smem = A tile, write out[j, i0+t]
//   Both walk stores at stride NOUT (1KB) inside contiguous 16KB segments.
//   __launch_bounds__(256,5) -> <=51 regs -> 5 CTAs/SM.
// ---------------------------------------------------------------------------
__global__ void __launch_bounds__(256, 5)
sym_writer_kernel(float* __restrict__ out)
{
    int bj = blockIdx.x;
    int bi = blockIdx.y;
    bool mirror = false;
    if (bi > bj) {                    // remap lower -> strict-upper twin
        bi = (NT - 1) - bi;
        bj = (NT - 1) - bj;
        mirror = true;
    }
    const bool diag = (bi == bj);     // diag => !mirror
    const int i0 = bi * TS;
    const int j0 = bj * TS;

    // role swap: outer rows go to regs, inner tile to smem
    const float* outer0 = mirror ? g_B0 : g_A0;
    const float* outer1 = mirror ? g_B1 : g_A1;
    const float* inner0 = mirror ? g_A0 : g_B0;
    const float* inner1 = mirror ? g_A1 : g_B1;
    const int outerBase = mirror ? j0 : i0;
    const int innerBase = mirror ? i0 : j0;

    __shared__ __align__(16) float sI[TS * NOUT];    // 16 KB inner tile

    const int tid = threadIdx.x;
    const int c   = (tid & 63) * 4;   // channel offset (float4 lane)
    const int ip  = tid >> 6;         // outer-row sub-index 0..3

    // Wait until the GEMM grid's writes to g_* are visible.
    asm volatile("griddepcontrol.wait;" ::: "memory");

    // ---- outer rows into registers (coalesced float4) ----
    float4 oR[4];
    #pragma unroll
    for (int ob = 0; ob < 4; ob++) {
        int r = outerBase + ob * 4 + ip;
        float4 p0 = *reinterpret_cast<const float4*>(&outer0[r * NOUT + c]);
        float4 p1 = *reinterpret_cast<const float4*>(&outer1[r * NOUT + c]);
        oR[ob] = make_float4(p0.x + p1.x, p0.y + p1.y, p0.z + p1.z, p0.w + p1.w);
    }

    // ---- inner tile into smem (coalesced float4) ----
    #pragma unroll
    for (int s = 0; s < 4; s++) {
        int idx = tid + s * 256;      // float4 slot 0..1023
        int r   = idx >> 6;           // row 0..15
        int cc  = (idx & 63) * 4;
        float4 p0 = *reinterpret_cast<const float4*>(&inner0[(innerBase + r) * NOUT + cc]);
        float4 p1 = *reinterpret_cast<const float4*>(&inner1[(innerBase + r) * NOUT + cc]);
        *reinterpret_cast<float4*>(&sI[r * NOUT + cc]) =
            make_float4(p0.x + p1.x, p0.y + p1.y, p0.z + p1.z, p0.w + p1.w);
    }
    __syncthreads();

    if (!diag) {
        #pragma unroll
        for (int ob = 0; ob < 4; ob++) {
            const int r = outerBase + ob * 4 + ip;   // global row of out
            const float4 a = oR[ob];
            float* p = &out[((size_t)r * NNODES + innerBase) * NOUT + c];
            #pragma unroll
            for (int t = 0; t < TS; t++) {
                float4 bb = *reinterpret_cast<const float4*>(&sI[t * NOUT + c]);
                float4 v  = make_float4(a.x + bb.x, a.y + bb.y,
                                        a.z + bb.z, a.w + bb.w);
                __stcs(reinterpret_cast<float4*>(p), v);
                p += NOUT;
            }
        }
    } else {
        // diagonal tile (non-mirror): regs = A rows, smem = B tile.
        // Write strict-upper pairs + both copies + zero diagonal.
        #pragma unroll
        for (int ob = 0; ob < 4; ob++) {
            const int ii = ob * 4 + ip;
            const int i  = i0 + ii;
            const float4 a = oR[ob];
            float* pij = &out[((size_t)i * NNODES + (j0 + ii + 1)) * NOUT + c];
            float* pji = &out[((size_t)(j0 + ii + 1) * NNODES + i) * NOUT + c];
            for (int jj = ii + 1; jj < TS; jj++) {
                float4 bb = *reinterpret_cast<const float4*>(&sI[jj * NOUT + c]);
                float4 v  = make_float4(a.x + bb.x, a.y + bb.y,
                                        a.z + bb.z, a.w + bb.w);
                __stcs(reinterpret_cast<float4*>(pij), v);
                __stcs(reinterpret_cast<float4*>(pji), v);
                pij += NOUT;
                pji += (size_t)NNODES * NOUT;
            }
            __stcs(reinterpret_cast<float4*>(
                &out[((size_t)i * NNODES + i) * NOUT + c]),
                make_float4(0.f, 0.f, 0.f, 0.f));
        }
    }
}

extern "C" void kernel_launch(void* const* d_in, const int* in_sizes, int n_in,
                              void* d_out, int out_size)
{
    const float* x = (const float*)d_in[0];   // [512, 256]
    const float* W = (const float*)d_in[1];   // [256, 512]
    const float* b = (const float*)d_in[2];   // [256]
    float* out = (float*)d_out;               // [512, 512, 256]

    // Kernel 1: split-K partials (512 blocks x 128 threads)
    gemm_ab_kernel<<<dim3(8, 16, 4), 128>>>(x, W, b);

    // Kernel 2: symmetric writer with PDL overlap of the GEMM tail.
    cudaLaunchConfig_t cfg = {};
    cfg.gridDim  = dim3(NT, NT, 1);
    cfg.blockDim = dim3(256, 1, 1);
    cfg.dynamicSmemBytes = 0;
    cfg.stream = 0;
    cudaLaunchAttribute attrs[1];
    attrs[0].id = cudaLaunchAttributeProgrammaticStreamSerialization;
    attrs[0].val.programmaticStreamSerializationAllowed = 1;
    cfg.attrs = attrs;
    cfg.numAttrs = 1;
    cudaLaunchKernelEx(&cfg, sym_writer_kernel, out);
}